// round 14
// baseline (speedup 1.0000x reference)
#include <cuda_runtime.h>
#include <cstdint>

#define NN 64
#define TT 512
#define VV 25
#define CIN 3
#define CH 64
#define FF 25
#define G4 100          // 4*FF

#define TCHUNK 8        // t per block in kernel 1 (processed as 4 pairs)

// Scratch (device globals: allocation-free rule)
__device__ float g_zx[NN * TT * VV * G4];   // (n,t,v,g)  327.7 MB
__device__ float g_f1[NN * TT * VV * FF];   // (n,t,v,f)   81.9 MB

__device__ __forceinline__ float hsig(float x) {
    return __saturatef(fmaf(0.2f, x, 0.5f));
}

// ---- packed f32x2 helpers --------------------------------------------------
__device__ __forceinline__ uint64_t pack2(float lo, float hi) {
    uint64_t r;
    asm("mov.b64 %0, {%1, %2};" : "=l"(r) : "f"(lo), "f"(hi));
    return r;
}
__device__ __forceinline__ void ffma2(uint64_t& d, uint64_t a, uint64_t b) {
    asm("fma.rn.f32x2 %0, %1, %2, %0;" : "+l"(d) : "l"(a), "l"(b));
}
__device__ __forceinline__ float hsum2(uint64_t v) {
    float lo, hi;
    asm("mov.b64 {%0, %1}, %2;" : "=f"(lo), "=f"(hi) : "l"(v));
    return lo + hi;
}

// ---------------------------------------------------------------------------
// Kernel 1: zx[n,t,v,:] = relu(x[n,t,v,:] @ Wc + bc) @ Wl + bl
// (unchanged from R13 passing version: 403 us measured)
// ---------------------------------------------------------------------------
__global__ __launch_bounds__(128, 2) void k_conv_z(
    const float* __restrict__ X,
    const float* __restrict__ Wc, const float* __restrict__ bc,
    const float* __restrict__ Wl, const float* __restrict__ bl)
{
    __shared__ float wc_s[CIN * CH];
    __shared__ float bc_s[CH];
    __shared__ __align__(16) float x1s[2][VV * CH];   // per-group x1 tiles

    const int tid = threadIdx.x;
    const int n = blockIdx.y;
    const int t0 = blockIdx.x * TCHUNK;

    for (int i = tid; i < CIN * CH; i += 128) wc_s[i] = Wc[i];
    if (tid < CH) bc_s[tid] = bc[tid];

    const int grp = tid >> 6;            // 0: even t, 1: odd t
    const int idx = tid & 63;            // id within group
    const int g = idx;                   // gate columns g and g+50
    const bool act = idx < 50;

    uint64_t wA[CH / 2], wB[CH / 2];     // packed c-pair weights for g, g+50
    float blA = 0.f, blB = 0.f;
    if (act) {
        blA = bl[g];
        blB = bl[g + 50];
#pragma unroll
        for (int j = 0; j < CH / 2; ++j) {
            wA[j] = pack2(Wl[(2 * j) * G4 + g],      Wl[(2 * j + 1) * G4 + g]);
            wB[j] = pack2(Wl[(2 * j) * G4 + g + 50], Wl[(2 * j + 1) * G4 + g + 50]);
        }
    }
    __syncthreads();

    for (int tp = 0; tp < TCHUNK / 2; ++tp) {
        const int tb = t0 + 2 * tp;                 // group 0 -> tb, group 1 -> tb+1

        // stage 1: both x1 tiles (2 x 25 x 64), all 128 threads
        for (int i = tid; i < 2 * VV * CH; i += 128) {
            const int tile = i / (VV * CH);
            const int rem = i - tile * (VV * CH);
            const int v = rem >> 6, c = rem & 63;
            const float* xr = X + (size_t)((n * TT + tb + tile) * VV + v) * CIN;
            float a = bc_s[c];
            a = fmaf(xr[0], wc_s[c],          a);
            a = fmaf(xr[1], wc_s[CH + c],     a);
            a = fmaf(xr[2], wc_s[2 * CH + c], a);
            x1s[tile][rem] = fmaxf(a, 0.f);
        }
        __syncthreads();

        // stage 2: each group does its own t with its own tile
        if (act) {
            const int t = tb + grp;
            const int rowbase = (n * TT + t) * VV;
            float* zbase = g_zx + (size_t)rowbase * G4;
            const float* xt = x1s[grp];
            for (int v = 0; v < VV; ++v) {
                const ulonglong2* xv = (const ulonglong2*)(xt + v * CH);
                uint64_t a0 = pack2(blA, 0.f), a1 = 0, a2 = 0, a3 = 0;
                uint64_t b0 = pack2(blB, 0.f), b1 = 0, b2 = 0, b3 = 0;
#pragma unroll
                for (int q = 0; q < 8; ++q) {
                    ulonglong2 p0 = xv[2 * q];         // floats {8q..8q+3}
                    ulonglong2 p1 = xv[2 * q + 1];     // floats {8q+4..8q+7}
                    ffma2(a0, p0.x, wA[4 * q + 0]);
                    ffma2(b0, p0.x, wB[4 * q + 0]);
                    ffma2(a1, p0.y, wA[4 * q + 1]);
                    ffma2(b1, p0.y, wB[4 * q + 1]);
                    ffma2(a2, p1.x, wA[4 * q + 2]);
                    ffma2(b2, p1.x, wB[4 * q + 2]);
                    ffma2(a3, p1.y, wA[4 * q + 3]);
                    ffma2(b3, p1.y, wB[4 * q + 3]);
                }
                zbase[v * G4 + g] =
                    (hsum2(a0) + hsum2(a1)) + (hsum2(a2) + hsum2(a3));
                zbase[v * G4 + g + 50] =
                    (hsum2(b0) + hsum2(b1)) + (hsum2(b2) + hsum2(b3));
            }
        }
        __syncthreads();
    }
}

// ---------------------------------------------------------------------------
// Kernel 2: ConvLSTM recurrence, warp-per-(n,v), barrier-free.
// CHANGE: 2-deep z prefetch pipeline (issue z(t+2) while computing t) so the
// ~400-577cyc DRAM latency is hidden behind two per-t compute periods.
// ---------------------------------------------------------------------------
__global__ __launch_bounds__(128) void k_lstm(const float* __restrict__ U)
{
    const int lane = threadIdx.x & 31;
    const int wrp  = threadIdx.x >> 5;
    const int seq  = blockIdx.x * 4 + wrp;       // 0..1599
    const int n = seq / VV, v = seq % VV;
    const bool act = lane < FF;

    float ui[FF], uf[FF], ug[FF], uo[FF];
#pragma unroll
    for (int c = 0; c < FF; ++c) {
        const float* Ur = U + c * G4;
        ui[c] = act ? Ur[lane]           : 0.f;
        uf[c] = act ? Ur[FF + lane]      : 0.f;
        ug[c] = act ? Ur[2 * FF + lane]  : 0.f;
        uo[c] = act ? Ur[3 * FF + lane]  : 0.f;
    }

    const size_t zstride = (size_t)VV * G4;
    const float* zrow = g_zx + ((size_t)(n * TT) * VV + v) * G4;

    float h = 0.f, cst = 0.f;

    // prefetch pipeline: cur = z(t), nx = z(t+1)
    float ci = 0.f, cf_ = 0.f, cg = 0.f, co = 0.f;
    float ni = 0.f, nf = 0.f, ng = 0.f, no = 0.f;
    if (act) {
        ci = zrow[lane];            cf_ = zrow[FF + lane];
        cg = zrow[2 * FF + lane];   co  = zrow[3 * FF + lane];
        const float* z1 = zrow + zstride;
        ni = z1[lane];              nf = z1[FF + lane];
        ng = z1[2 * FF + lane];     no = z1[3 * FF + lane];
    }

    float* frow = g_f1 + ((size_t)(n * TT) * VV + v) * FF;

    for (int t = 0; t < TT; ++t) {
        // issue z(t+2) now; consumed two iterations later
        float fi = 0.f, ff = 0.f, fg = 0.f, fo = 0.f;
        if (act && t + 2 < TT) {
            const float* z2 = zrow + (size_t)(t + 2) * zstride;
            fi = z2[lane]; ff = z2[FF + lane];
            fg = z2[2 * FF + lane]; fo = z2[3 * FF + lane];
        }

        float gi = ci, gf = cf_, gg = cg, go = co;
#pragma unroll
        for (int c = 0; c < FF; ++c) {
            const float hc = __shfl_sync(0xFFFFFFFFu, h, c);
            gi = fmaf(hc, ui[c], gi);
            gf = fmaf(hc, uf[c], gf);
            gg = fmaf(hc, ug[c], gg);
            go = fmaf(hc, uo[c], go);
        }
        cst = hsig(gf) * cst + hsig(gi) * tanhf(gg);
        h = hsig(go) * tanhf(cst);

        if (act) frow[(size_t)t * (VV * FF) + lane] = h;

        ci = ni; cf_ = nf; cg = ng; co = no;
        ni = fi; nf = ff;  ng = fg; no = fo;
    }
}

// ---------------------------------------------------------------------------
// Kernel 3: attention + aggregation, warp-per-timestep.
// CHANGE: X tile (25x3 floats) staged into shared once per t; x1 recompute
// reads broadcast LDS instead of 64x-redundant global loads.
// ---------------------------------------------------------------------------
__global__ __launch_bounds__(128) void k_attn(
    const float* __restrict__ X,
    const float* __restrict__ Wc, const float* __restrict__ bc,
    const float* __restrict__ Bm, float* __restrict__ out)
{
    __shared__ float wc_s[CIN * CH];
    __shared__ float bc_s[CH];
    __shared__ float bias_s[VV * VV];
    __shared__ __align__(16) float x1w[4][VV * CH];   // per-warp x1 [v][c]
    __shared__ float cfw[4][26 * 28];                 // per-warp coefs, padded
    __shared__ float xsw[4][VV][4];                   // per-warp staged X rows

    const int tid = threadIdx.x;
    const int lane = tid & 31, wrp = tid >> 5;
    const int n = blockIdx.y;
    const int t0 = blockIdx.x * 16 + wrp * 4;

    for (int i = tid; i < CIN * CH; i += 128) wc_s[i] = Wc[i];
    if (tid < CH) bc_s[tid] = bc[tid];
    for (int i = tid; i < VV * VV; i += 128) bias_s[i] = Bm[i];
    __syncthreads();

    float* x1s = x1w[wrp];
    float* cfs = cfw[wrp];
    const int cq = lane & 15, vg = lane >> 4;
    const int vbase = vg ? 13 : 0;
    const int nv = vg ? 12 : 13;

    for (int it = 0; it < 4; ++it) {
        const int t = t0 + it;
        const int rowbase = (n * TT + t) * VV;

        // stage X tile: 25 rows x 3 floats, one row per lane
        if (lane < VV) {
            const float* xr = X + (size_t)(rowbase + lane) * CIN;
            xsw[wrp][lane][0] = xr[0];
            xsw[wrp][lane][1] = xr[1];
            xsw[wrp][lane][2] = xr[2];
        }

        // softmax: lane-per-row v (independent of xs)
        if (lane < VV) {
            const int v = lane;
            const float* fr = g_f1 + (size_t)rowbase * FF + v * FF;
            float e[VV], s = 0.f;
#pragma unroll
            for (int w_ = 0; w_ < VV; ++w_) {
                const float hv = fr[w_];
                const float lr = hv > 0.f ? hv : 0.2f * hv;
                const float ev = __expf(lr + bias_s[v * VV + w_]);
                e[w_] = ev; s += ev;
            }
            const float inv = 1.0f / s;
#pragma unroll
            for (int w_ = 0; w_ < VV; ++w_) cfs[v * 28 + w_] = e[w_] * inv;
        }
        __syncwarp();

        // x1 recompute from staged X (broadcast LDS, no global loads)
        for (int idx = lane; idx < VV * CH; idx += 32) {
            const int v = idx >> 6, c = idx & 63;
            float a = bc_s[c];
            a = fmaf(xsw[wrp][v][0], wc_s[c], a);
            a = fmaf(xsw[wrp][v][1], wc_s[CH + c], a);
            a = fmaf(xsw[wrp][v][2], wc_s[2 * CH + c], a);
            x1s[idx] = fmaxf(a, 0.f);
        }
        __syncwarp();

        // aggregation: lane = (vg, cq); 13 (or 12) v's per lane, 4 channels
        {
            float4 acc[13];
#pragma unroll
            for (int i = 0; i < 13; ++i) acc[i] = make_float4(0.f, 0.f, 0.f, 0.f);
            const float4* x4 = (const float4*)x1s;
#pragma unroll
            for (int w_ = 0; w_ < VV; ++w_) {
                const float4 xv = x4[w_ * 16 + cq];
#pragma unroll
                for (int vl = 0; vl < 13; ++vl) {
                    const float cv = cfs[(vbase + vl) * 28 + w_];
                    acc[vl].x = fmaf(cv, xv.x, acc[vl].x);
                    acc[vl].y = fmaf(cv, xv.y, acc[vl].y);
                    acc[vl].z = fmaf(cv, xv.z, acc[vl].z);
                    acc[vl].w = fmaf(cv, xv.w, acc[vl].w);
                }
            }
#pragma unroll
            for (int vl = 0; vl < 13; ++vl) {
                if (vl < nv) {
                    const int v = vbase + vl;
                    *(float4*)(out + (size_t)(rowbase + v) * CH + cq * 4) = acc[vl];
                }
            }
        }
        __syncwarp();
    }
}

// ---------------------------------------------------------------------------
extern "C" void kernel_launch(void* const* d_in, const int* in_sizes, int n_in,
                              void* d_out, int out_size)
{
    const float* X  = (const float*)d_in[0];
    const float* Wc = (const float*)d_in[1];
    const float* bc = (const float*)d_in[2];
    const float* Wl = (const float*)d_in[3];
    const float* Ul = (const float*)d_in[4];
    const float* bl = (const float*)d_in[5];
    const float* Bm = (const float*)d_in[6];
    float* out = (float*)d_out;

    k_conv_z<<<dim3(TT / TCHUNK, NN), 128>>>(X, Wc, bc, Wl, bl);
    k_lstm<<<NN * VV / 4, 128>>>(Ul);
    k_attn<<<dim3(TT / 16, NN), 128>>>(X, Wc, bc, Bm, out);
}

// round 15
// speedup vs baseline: 1.0294x; 1.0294x over previous
#include <cuda_runtime.h>
#include <cstdint>

#define NN 64
#define TT 512
#define VV 25
#define CIN 3
#define CH 64
#define FF 25
#define G4 100          // 4*FF

#define TCHUNK 8        // t per block in kernel 1 (processed as 4 pairs)

// Scratch (device globals: allocation-free rule)
__device__ float g_zx[NN * TT * VV * G4];   // (n,t,v,g)  327.7 MB
__device__ float g_f1[NN * TT * VV * FF];   // (n,t,v,f)   81.9 MB

__device__ __forceinline__ float hsig(float x) {
    return __saturatef(fmaf(0.2f, x, 0.5f));
}

// ---- packed f32x2 helpers --------------------------------------------------
__device__ __forceinline__ uint64_t pack2(float lo, float hi) {
    uint64_t r;
    asm("mov.b64 %0, {%1, %2};" : "=l"(r) : "f"(lo), "f"(hi));
    return r;
}
__device__ __forceinline__ void ffma2(uint64_t& d, uint64_t a, uint64_t b) {
    asm("fma.rn.f32x2 %0, %1, %2, %0;" : "+l"(d) : "l"(a), "l"(b));
}
__device__ __forceinline__ float hsum2(uint64_t v) {
    float lo, hi;
    asm("mov.b64 {%0, %1}, %2;" : "=f"(lo), "=f"(hi) : "l"(v));
    return lo + hi;
}

// ---------------------------------------------------------------------------
// Kernel 1: zx[n,t,v,:] = relu(x[n,t,v,:] @ Wc + bc) @ Wl + bl
// (unchanged from R13 passing version: 403 us measured)
// ---------------------------------------------------------------------------
__global__ __launch_bounds__(128, 2) void k_conv_z(
    const float* __restrict__ X,
    const float* __restrict__ Wc, const float* __restrict__ bc,
    const float* __restrict__ Wl, const float* __restrict__ bl)
{
    __shared__ float wc_s[CIN * CH];
    __shared__ float bc_s[CH];
    __shared__ __align__(16) float x1s[2][VV * CH];   // per-group x1 tiles

    const int tid = threadIdx.x;
    const int n = blockIdx.y;
    const int t0 = blockIdx.x * TCHUNK;

    for (int i = tid; i < CIN * CH; i += 128) wc_s[i] = Wc[i];
    if (tid < CH) bc_s[tid] = bc[tid];

    const int grp = tid >> 6;            // 0: even t, 1: odd t
    const int idx = tid & 63;            // id within group
    const int g = idx;                   // gate columns g and g+50
    const bool act = idx < 50;

    uint64_t wA[CH / 2], wB[CH / 2];     // packed c-pair weights for g, g+50
    float blA = 0.f, blB = 0.f;
    if (act) {
        blA = bl[g];
        blB = bl[g + 50];
#pragma unroll
        for (int j = 0; j < CH / 2; ++j) {
            wA[j] = pack2(Wl[(2 * j) * G4 + g],      Wl[(2 * j + 1) * G4 + g]);
            wB[j] = pack2(Wl[(2 * j) * G4 + g + 50], Wl[(2 * j + 1) * G4 + g + 50]);
        }
    }
    __syncthreads();

    for (int tp = 0; tp < TCHUNK / 2; ++tp) {
        const int tb = t0 + 2 * tp;                 // group 0 -> tb, group 1 -> tb+1

        // stage 1: both x1 tiles (2 x 25 x 64), all 128 threads
        for (int i = tid; i < 2 * VV * CH; i += 128) {
            const int tile = i / (VV * CH);
            const int rem = i - tile * (VV * CH);
            const int v = rem >> 6, c = rem & 63;
            const float* xr = X + (size_t)((n * TT + tb + tile) * VV + v) * CIN;
            float a = bc_s[c];
            a = fmaf(xr[0], wc_s[c],          a);
            a = fmaf(xr[1], wc_s[CH + c],     a);
            a = fmaf(xr[2], wc_s[2 * CH + c], a);
            x1s[tile][rem] = fmaxf(a, 0.f);
        }
        __syncthreads();

        // stage 2: each group does its own t with its own tile
        if (act) {
            const int t = tb + grp;
            const int rowbase = (n * TT + t) * VV;
            float* zbase = g_zx + (size_t)rowbase * G4;
            const float* xt = x1s[grp];
            for (int v = 0; v < VV; ++v) {
                const ulonglong2* xv = (const ulonglong2*)(xt + v * CH);
                uint64_t a0 = pack2(blA, 0.f), a1 = 0, a2 = 0, a3 = 0;
                uint64_t b0 = pack2(blB, 0.f), b1 = 0, b2 = 0, b3 = 0;
#pragma unroll
                for (int q = 0; q < 8; ++q) {
                    ulonglong2 p0 = xv[2 * q];         // floats {8q..8q+3}
                    ulonglong2 p1 = xv[2 * q + 1];     // floats {8q+4..8q+7}
                    ffma2(a0, p0.x, wA[4 * q + 0]);
                    ffma2(b0, p0.x, wB[4 * q + 0]);
                    ffma2(a1, p0.y, wA[4 * q + 1]);
                    ffma2(b1, p0.y, wB[4 * q + 1]);
                    ffma2(a2, p1.x, wA[4 * q + 2]);
                    ffma2(b2, p1.x, wB[4 * q + 2]);
                    ffma2(a3, p1.y, wA[4 * q + 3]);
                    ffma2(b3, p1.y, wB[4 * q + 3]);
                }
                zbase[v * G4 + g] =
                    (hsum2(a0) + hsum2(a1)) + (hsum2(a2) + hsum2(a3));
                zbase[v * G4 + g + 50] =
                    (hsum2(b0) + hsum2(b1)) + (hsum2(b2) + hsum2(b3));
            }
        }
        __syncthreads();
    }
}

// ---------------------------------------------------------------------------
// Kernel 2: ConvLSTM recurrence, warp-per-(n,v), barrier-free.
// (reverted to R12/R13 1-deep prefetch version — part of the 869us baseline)
// ---------------------------------------------------------------------------
__global__ __launch_bounds__(128) void k_lstm(const float* __restrict__ U)
{
    const int lane = threadIdx.x & 31;
    const int wrp  = threadIdx.x >> 5;
    const int seq  = blockIdx.x * 4 + wrp;       // 0..1599
    const int n = seq / VV, v = seq % VV;
    const bool act = lane < FF;

    float ui[FF], uf[FF], ug[FF], uo[FF];
#pragma unroll
    for (int c = 0; c < FF; ++c) {
        const float* Ur = U + c * G4;
        ui[c] = act ? Ur[lane]           : 0.f;
        uf[c] = act ? Ur[FF + lane]      : 0.f;
        ug[c] = act ? Ur[2 * FF + lane]  : 0.f;
        uo[c] = act ? Ur[3 * FF + lane]  : 0.f;
    }

    const size_t zstride = (size_t)VV * G4;
    const float* zrow = g_zx + ((size_t)(n * TT) * VV + v) * G4;

    float h = 0.f, cst = 0.f;

    float zi = act ? zrow[lane]          : 0.f;
    float zf = act ? zrow[FF + lane]     : 0.f;
    float zg = act ? zrow[2 * FF + lane] : 0.f;
    float zo = act ? zrow[3 * FF + lane] : 0.f;

    float* frow = g_f1 + ((size_t)(n * TT) * VV + v) * FF;

    for (int t = 0; t < TT; ++t) {
        float pi = 0.f, pf = 0.f, pg = 0.f, po = 0.f;
        if (t + 1 < TT && act) {
            const float* zn = zrow + (size_t)(t + 1) * zstride;
            pi = zn[lane]; pf = zn[FF + lane];
            pg = zn[2 * FF + lane]; po = zn[3 * FF + lane];
        }

        float gi = zi, gf = zf, gg = zg, go = zo;
#pragma unroll
        for (int c = 0; c < FF; ++c) {
            const float hc = __shfl_sync(0xFFFFFFFFu, h, c);
            gi = fmaf(hc, ui[c], gi);
            gf = fmaf(hc, uf[c], gf);
            gg = fmaf(hc, ug[c], gg);
            go = fmaf(hc, uo[c], go);
        }
        cst = hsig(gf) * cst + hsig(gi) * tanhf(gg);
        h = hsig(go) * tanhf(cst);

        if (act) frow[(size_t)t * (VV * FF) + lane] = h;

        zi = pi; zf = pf; zg = pg; zo = po;
    }
}

// ---------------------------------------------------------------------------
// Kernel 3: attention + aggregation, warp-per-timestep.
// CHANGE vs 869 baseline: f1 row (625 contiguous floats) staged into shared
// with coalesced lane-striped loads (20 LDG/warp-t vs ~500 uncoalesced
// wavefronts); softmax reads smem (lane*25+w is conflict-free, gcd(25,32)=1).
// ---------------------------------------------------------------------------
__global__ __launch_bounds__(128) void k_attn(
    const float* __restrict__ X,
    const float* __restrict__ Wc, const float* __restrict__ bc,
    const float* __restrict__ Bm, float* __restrict__ out)
{
    __shared__ float wc_s[CIN * CH];
    __shared__ float bc_s[CH];
    __shared__ float bias_s[VV * VV];
    __shared__ __align__(16) float x1w[4][VV * CH];   // per-warp x1 [v][c]
    __shared__ float cfw[4][26 * 28];                 // per-warp coefs, padded
    __shared__ float fsw[4][VV * VV];                 // per-warp staged f1 tile

    const int tid = threadIdx.x;
    const int lane = tid & 31, wrp = tid >> 5;
    const int n = blockIdx.y;
    const int t0 = blockIdx.x * 16 + wrp * 4;

    for (int i = tid; i < CIN * CH; i += 128) wc_s[i] = Wc[i];
    if (tid < CH) bc_s[tid] = bc[tid];
    for (int i = tid; i < VV * VV; i += 128) bias_s[i] = Bm[i];
    __syncthreads();

    float* x1s = x1w[wrp];
    float* cfs = cfw[wrp];
    float* fss = fsw[wrp];
    const int cq = lane & 15, vg = lane >> 4;
    const int vbase = vg ? 13 : 0;
    const int nv = vg ? 12 : 13;

    for (int it = 0; it < 4; ++it) {
        const int t = t0 + it;
        const int rowbase = (n * TT + t) * VV;

        // stage f1 tile: 625 contiguous floats, coalesced lane-striped
        {
            const float* fr = g_f1 + (size_t)rowbase * FF;
#pragma unroll
            for (int i = 0; i < 19; ++i)
                fss[i * 32 + lane] = fr[i * 32 + lane];
            if (lane < VV * VV - 19 * 32)
                fss[19 * 32 + lane] = fr[19 * 32 + lane];
        }

        // x1 recompute into per-warp shared [v][c] (as in 869 baseline)
        for (int idx = lane; idx < VV * CH; idx += 32) {
            const int v = idx >> 6, c = idx & 63;
            const float* xr = X + (size_t)(rowbase + v) * CIN;
            float a = bc_s[c];
            a = fmaf(xr[0], wc_s[c], a);
            a = fmaf(xr[1], wc_s[CH + c], a);
            a = fmaf(xr[2], wc_s[2 * CH + c], a);
            x1s[idx] = fmaxf(a, 0.f);
        }
        __syncwarp();

        // softmax: lane-per-row v, reading staged f1 from smem
        if (lane < VV) {
            const int v = lane;
            float e[VV], s = 0.f;
#pragma unroll
            for (int w_ = 0; w_ < VV; ++w_) {
                const float hv = fss[v * VV + w_];
                const float lr = hv > 0.f ? hv : 0.2f * hv;
                const float ev = __expf(lr + bias_s[v * VV + w_]);
                e[w_] = ev; s += ev;
            }
            const float inv = 1.0f / s;
#pragma unroll
            for (int w_ = 0; w_ < VV; ++w_) cfs[v * 28 + w_] = e[w_] * inv;
        }
        __syncwarp();

        // aggregation: lane = (vg, cq); 13 (or 12) v's per lane, 4 channels
        {
            float4 acc[13];
#pragma unroll
            for (int i = 0; i < 13; ++i) acc[i] = make_float4(0.f, 0.f, 0.f, 0.f);
            const float4* x4 = (const float4*)x1s;
#pragma unroll
            for (int w_ = 0; w_ < VV; ++w_) {
                const float4 xv = x4[w_ * 16 + cq];
#pragma unroll
                for (int vl = 0; vl < 13; ++vl) {
                    const float cv = cfs[(vbase + vl) * 28 + w_];
                    acc[vl].x = fmaf(cv, xv.x, acc[vl].x);
                    acc[vl].y = fmaf(cv, xv.y, acc[vl].y);
                    acc[vl].z = fmaf(cv, xv.z, acc[vl].z);
                    acc[vl].w = fmaf(cv, xv.w, acc[vl].w);
                }
            }
#pragma unroll
            for (int vl = 0; vl < 13; ++vl) {
                if (vl < nv) {
                    const int v = vbase + vl;
                    *(float4*)(out + (size_t)(rowbase + v) * CH + cq * 4) = acc[vl];
                }
            }
        }
        __syncwarp();
    }
}

// ---------------------------------------------------------------------------
extern "C" void kernel_launch(void* const* d_in, const int* in_sizes, int n_in,
                              void* d_out, int out_size)
{
    const float* X  = (const float*)d_in[0];
    const float* Wc = (const float*)d_in[1];
    const float* bc = (const float*)d_in[2];
    const float* Wl = (const float*)d_in[3];
    const float* Ul = (const float*)d_in[4];
    const float* bl = (const float*)d_in[5];
    const float* Bm = (const float*)d_in[6];
    float* out = (float*)d_out;

    k_conv_z<<<dim3(TT / TCHUNK, NN), 128>>>(X, Wc, bc, Wl, bl);
    k_lstm<<<NN * VV / 4, 128>>>(Ul);
    k_attn<<<dim3(TT / 16, NN), 128>>>(X, Wc, bc, Bm, out);
}

// round 16
// speedup vs baseline: 1.3083x; 1.2708x over previous
#include <cuda_runtime.h>
#include <cuda_bf16.h>
#include <mma.h>
#include <cstdint>

using namespace nvcuda;

#define NN 64
#define TT 512
#define VV 25
#define CIN 3
#define CH 64
#define FF 25
#define G4 100          // 4*FF
#define NPAD 112        // G4 padded to 7 wmma n-tiles
#define ALD 72          // A tile leading dim (bf16 elems)

// Scratch (device globals: allocation-free rule)
__device__ float g_zx[NN * TT * VV * G4];   // (n,t,v,g)  327.7 MB
__device__ float g_f1[NN * TT * VV * FF];   // (n,t,v,f)   81.9 MB
__device__ __align__(32) __nv_bfloat16 g_Whi[CH * NPAD];
__device__ __align__(32) __nv_bfloat16 g_Wlo[CH * NPAD];
__device__ __align__(32) float g_biasf[16 * NPAD];   // 16 identical bias rows

__device__ __forceinline__ float hsig(float x) {
    return __saturatef(fmaf(0.2f, x, 0.5f));
}

// ---------------------------------------------------------------------------
// Prep: split W_lstm -> bf16 hi/lo [64][112]; build bias tile [16][112] f32.
// ---------------------------------------------------------------------------
__global__ void k_prep(const float* __restrict__ Wl, const float* __restrict__ bl)
{
    const int i = blockIdx.x * 128 + threadIdx.x;
    if (i < CH * NPAD) {
        const int r = i / NPAD, c = i % NPAD;
        const float v = (c < G4) ? Wl[r * G4 + c] : 0.f;
        const __nv_bfloat16 hi = __float2bfloat16(v);
        g_Whi[i] = hi;
        g_Wlo[i] = __float2bfloat16(v - __bfloat162float(hi));
    } else if (i < CH * NPAD + 16 * NPAD) {
        const int j = i - CH * NPAD;
        const int c = j % NPAD;
        g_biasf[j] = (c < G4) ? bl[c] : 0.f;
    }
}

// ---------------------------------------------------------------------------
// Kernel 1: z = relu(x@Wc+bc) @ Wl + bl  via split-bf16 WMMA (HMMA).
// Block = 128 GEMM rows; 4 warps, each owns 2 m-tiles x 7 n-tiles.
// acc = A_hi*B_hi + A_lo*B_hi + A_hi*B_lo + bias  (lo*lo dropped, ~2^-18).
// ---------------------------------------------------------------------------
__global__ __launch_bounds__(128) void k_conv_z(
    const float* __restrict__ X,
    const float* __restrict__ Wc, const float* __restrict__ bc)
{
    __shared__ __align__(32) __nv_bfloat16 Ahi[128 * ALD];
    __shared__ __align__(32) __nv_bfloat16 Alo[128 * ALD];
    __shared__ __align__(32) float cw[4][16 * 20];   // per-warp epilogue tile
    __shared__ float wc_s[CIN * CH];
    __shared__ float bc_s[CH];

    const int tid = threadIdx.x;
    const size_t R0 = (size_t)blockIdx.x * 128;

    for (int i = tid; i < CIN * CH; i += 128) wc_s[i] = Wc[i];
    if (tid < CH) bc_s[tid] = bc[tid];
    __syncthreads();

    // stage 1: row r = tid; compute x1 row, split into bf16 hi/lo tiles
    {
        const int r = tid;
        const float* xr = X + (R0 + r) * CIN;
        const float x0 = xr[0], x1v = xr[1], x2 = xr[2];
#pragma unroll
        for (int c2 = 0; c2 < CH / 2; ++c2) {
            const int c0 = 2 * c2, c1 = 2 * c2 + 1;
            float a0 = bc_s[c0];
            a0 = fmaf(x0, wc_s[c0], a0);
            a0 = fmaf(x1v, wc_s[CH + c0], a0);
            a0 = fmaf(x2, wc_s[2 * CH + c0], a0);
            a0 = fmaxf(a0, 0.f);
            float a1 = bc_s[c1];
            a1 = fmaf(x0, wc_s[c1], a1);
            a1 = fmaf(x1v, wc_s[CH + c1], a1);
            a1 = fmaf(x2, wc_s[2 * CH + c1], a1);
            a1 = fmaxf(a1, 0.f);
            const __nv_bfloat16 h0 = __float2bfloat16(a0);
            const __nv_bfloat16 h1 = __float2bfloat16(a1);
            __nv_bfloat162 hp; hp.x = h0; hp.y = h1;
            __nv_bfloat162 lp;
            lp.x = __float2bfloat16(a0 - __bfloat162float(h0));
            lp.y = __float2bfloat16(a1 - __bfloat162float(h1));
            *(__nv_bfloat162*)&Ahi[r * ALD + 2 * c2] = hp;
            *(__nv_bfloat162*)&Alo[r * ALD + 2 * c2] = lp;
        }
    }
    __syncthreads();

    // stage 2: WMMA
    const int w = tid >> 5, lane = tid & 31;

    wmma::fragment<wmma::matrix_a, 16, 16, 16, __nv_bfloat16, wmma::row_major> ah[2][4], al[2][4];
#pragma unroll
    for (int i = 0; i < 2; ++i) {
        const int mt = 2 * w + i;
#pragma unroll
        for (int k = 0; k < 4; ++k) {
            wmma::load_matrix_sync(ah[i][k], &Ahi[mt * 16 * ALD + k * 16], ALD);
            wmma::load_matrix_sync(al[i][k], &Alo[mt * 16 * ALD + k * 16], ALD);
        }
    }

    for (int nt = 0; nt < 7; ++nt) {
        wmma::fragment<wmma::accumulator, 16, 16, 16, float> acc[2];
        wmma::load_matrix_sync(acc[0], g_biasf + nt * 16, NPAD, wmma::mem_row_major);
        wmma::load_matrix_sync(acc[1], g_biasf + nt * 16, NPAD, wmma::mem_row_major);

#pragma unroll
        for (int k = 0; k < 4; ++k) {
            wmma::fragment<wmma::matrix_b, 16, 16, 16, __nv_bfloat16, wmma::row_major> bh, blo;
            wmma::load_matrix_sync(bh,  g_Whi + k * 16 * NPAD + nt * 16, NPAD);
            wmma::load_matrix_sync(blo, g_Wlo + k * 16 * NPAD + nt * 16, NPAD);
#pragma unroll
            for (int i = 0; i < 2; ++i) {
                wmma::mma_sync(acc[i], ah[i][k], bh,  acc[i]);
                wmma::mma_sync(acc[i], al[i][k], bh,  acc[i]);
                wmma::mma_sync(acc[i], ah[i][k], blo, acc[i]);
            }
        }

        // epilogue via per-warp smem tile -> aligned float4 STG (guard N=100)
#pragma unroll
        for (int i = 0; i < 2; ++i) {
            const int mt = 2 * w + i;
            wmma::store_matrix_sync(cw[w], acc[i], 20, wmma::mem_row_major);
            __syncwarp();
            {
                const int rr = lane >> 1, qh = lane & 1;
                const float4* src = (const float4*)&cw[w][rr * 20 + qh * 8];
                float* dst = g_zx + (R0 + mt * 16 + rr) * G4 + nt * 16 + qh * 8;
                if (nt < 6) {
                    *(float4*)dst = src[0];
                    *(float4*)(dst + 4) = src[1];
                } else if (qh == 0) {
                    *(float4*)dst = src[0];     // cols 96..99 only
                }
            }
            __syncwarp();
        }
    }
}

// ---------------------------------------------------------------------------
// Kernel 2: ConvLSTM recurrence, warp-per-(n,v), barrier-free.
// (unchanged from 862us baseline)
// ---------------------------------------------------------------------------
__global__ __launch_bounds__(128) void k_lstm(const float* __restrict__ U)
{
    const int lane = threadIdx.x & 31;
    const int wrp  = threadIdx.x >> 5;
    const int seq  = blockIdx.x * 4 + wrp;       // 0..1599
    const int n = seq / VV, v = seq % VV;
    const bool act = lane < FF;

    float ui[FF], uf[FF], ug[FF], uo[FF];
#pragma unroll
    for (int c = 0; c < FF; ++c) {
        const float* Ur = U + c * G4;
        ui[c] = act ? Ur[lane]           : 0.f;
        uf[c] = act ? Ur[FF + lane]      : 0.f;
        ug[c] = act ? Ur[2 * FF + lane]  : 0.f;
        uo[c] = act ? Ur[3 * FF + lane]  : 0.f;
    }

    const size_t zstride = (size_t)VV * G4;
    const float* zrow = g_zx + ((size_t)(n * TT) * VV + v) * G4;

    float h = 0.f, cst = 0.f;

    float zi = act ? zrow[lane]          : 0.f;
    float zf = act ? zrow[FF + lane]     : 0.f;
    float zg = act ? zrow[2 * FF + lane] : 0.f;
    float zo = act ? zrow[3 * FF + lane] : 0.f;

    float* frow = g_f1 + ((size_t)(n * TT) * VV + v) * FF;

    for (int t = 0; t < TT; ++t) {
        float pi = 0.f, pf = 0.f, pg = 0.f, po = 0.f;
        if (t + 1 < TT && act) {
            const float* zn = zrow + (size_t)(t + 1) * zstride;
            pi = zn[lane]; pf = zn[FF + lane];
            pg = zn[2 * FF + lane]; po = zn[3 * FF + lane];
        }

        float gi = zi, gf = zf, gg = zg, go = zo;
#pragma unroll
        for (int c = 0; c < FF; ++c) {
            const float hc = __shfl_sync(0xFFFFFFFFu, h, c);
            gi = fmaf(hc, ui[c], gi);
            gf = fmaf(hc, uf[c], gf);
            gg = fmaf(hc, ug[c], gg);
            go = fmaf(hc, uo[c], go);
        }
        cst = hsig(gf) * cst + hsig(gi) * tanhf(gg);
        h = hsig(go) * tanhf(cst);

        if (act) frow[(size_t)t * (VV * FF) + lane] = h;

        zi = pi; zf = pf; zg = pg; zo = po;
    }
}

// ---------------------------------------------------------------------------
// Kernel 3: attention + aggregation, warp-per-timestep.
// (unchanged from 862us baseline)
// ---------------------------------------------------------------------------
__global__ __launch_bounds__(128) void k_attn(
    const float* __restrict__ X,
    const float* __restrict__ Wc, const float* __restrict__ bc,
    const float* __restrict__ Bm, float* __restrict__ out)
{
    __shared__ float wc_s[CIN * CH];
    __shared__ float bc_s[CH];
    __shared__ float bias_s[VV * VV];
    __shared__ __align__(16) float x1w[4][VV * CH];   // per-warp x1 [v][c]
    __shared__ float cfw[4][26 * 28];                 // per-warp coefs, padded
    __shared__ float fsw[4][VV * VV];                 // per-warp staged f1 tile

    const int tid = threadIdx.x;
    const int lane = tid & 31, wrp = tid >> 5;
    const int n = blockIdx.y;
    const int t0 = blockIdx.x * 16 + wrp * 4;

    for (int i = tid; i < CIN * CH; i += 128) wc_s[i] = Wc[i];
    if (tid < CH) bc_s[tid] = bc[tid];
    for (int i = tid; i < VV * VV; i += 128) bias_s[i] = Bm[i];
    __syncthreads();

    float* x1s = x1w[wrp];
    float* cfs = cfw[wrp];
    float* fss = fsw[wrp];
    const int cq = lane & 15, vg = lane >> 4;
    const int vbase = vg ? 13 : 0;
    const int nv = vg ? 12 : 13;

    for (int it = 0; it < 4; ++it) {
        const int t = t0 + it;
        const int rowbase = (n * TT + t) * VV;

        // stage f1 tile: 625 contiguous floats, coalesced lane-striped
        {
            const float* fr = g_f1 + (size_t)rowbase * FF;
#pragma unroll
            for (int i = 0; i < 19; ++i)
                fss[i * 32 + lane] = fr[i * 32 + lane];
            if (lane < VV * VV - 19 * 32)
                fss[19 * 32 + lane] = fr[19 * 32 + lane];
        }

        // x1 recompute into per-warp shared [v][c]
        for (int idx = lane; idx < VV * CH; idx += 32) {
            const int v = idx >> 6, c = idx & 63;
            const float* xr = X + (size_t)(rowbase + v) * CIN;
            float a = bc_s[c];
            a = fmaf(xr[0], wc_s[c], a);
            a = fmaf(xr[1], wc_s[CH + c], a);
            a = fmaf(xr[2], wc_s[2 * CH + c], a);
            x1s[idx] = fmaxf(a, 0.f);
        }
        __syncwarp();

        // softmax: lane-per-row v, reading staged f1 from smem
        if (lane < VV) {
            const int v = lane;
            float e[VV], s = 0.f;
#pragma unroll
            for (int w_ = 0; w_ < VV; ++w_) {
                const float hv = fss[v * VV + w_];
                const float lr = hv > 0.f ? hv : 0.2f * hv;
                const float ev = __expf(lr + bias_s[v * VV + w_]);
                e[w_] = ev; s += ev;
            }
            const float inv = 1.0f / s;
#pragma unroll
            for (int w_ = 0; w_ < VV; ++w_) cfs[v * 28 + w_] = e[w_] * inv;
        }
        __syncwarp();

        // aggregation
        {
            float4 acc[13];
#pragma unroll
            for (int i = 0; i < 13; ++i) acc[i] = make_float4(0.f, 0.f, 0.f, 0.f);
            const float4* x4 = (const float4*)x1s;
#pragma unroll
            for (int w_ = 0; w_ < VV; ++w_) {
                const float4 xv = x4[w_ * 16 + cq];
#pragma unroll
                for (int vl = 0; vl < 13; ++vl) {
                    const float cv = cfs[(vbase + vl) * 28 + w_];
                    acc[vl].x = fmaf(cv, xv.x, acc[vl].x);
                    acc[vl].y = fmaf(cv, xv.y, acc[vl].y);
                    acc[vl].z = fmaf(cv, xv.z, acc[vl].z);
                    acc[vl].w = fmaf(cv, xv.w, acc[vl].w);
                }
            }
#pragma unroll
            for (int vl = 0; vl < 13; ++vl) {
                if (vl < nv) {
                    const int v = vbase + vl;
                    *(float4*)(out + (size_t)(rowbase + v) * CH + cq * 4) = acc[vl];
                }
            }
        }
        __syncwarp();
    }
}

// ---------------------------------------------------------------------------
extern "C" void kernel_launch(void* const* d_in, const int* in_sizes, int n_in,
                              void* d_out, int out_size)
{
    const float* X  = (const float*)d_in[0];
    const float* Wc = (const float*)d_in[1];
    const float* bc = (const float*)d_in[2];
    const float* Wl = (const float*)d_in[3];
    const float* Ul = (const float*)d_in[4];
    const float* bl = (const float*)d_in[5];
    const float* Bm = (const float*)d_in[6];
    float* out = (float*)d_out;

    k_prep<<<(CH * NPAD + 16 * NPAD + 127) / 128, 128>>>(Wl, bl);
    k_conv_z<<<NN * TT * VV / 128, 128>>>(X, Wc, bc);
    k_lstm<<<NN * VV / 4, 128>>>(Ul);
    k_attn<<<dim3(TT / 16, NN), 128>>>(X, Wc, bc, Bm, out);
}